// round 8
// baseline (speedup 1.0000x reference)
#include <cuda_runtime.h>

typedef unsigned long long ull;

#define Bsz   128
#define TM1   255
#define NIN   256
#define Hd    256
#define BT    (Bsz * TM1)      /* 32640 */
#define G4H   1024

// ---------------- device scratch (static allocation only) ----------------
__device__ float g_G[(size_t)BT * G4H];   // 133.7 MB: x_tilde@W + b

// ---------------- packed f32x2 helpers -----------------------------------
__device__ __forceinline__ ull pack2(float lo, float hi) {
    ull r; asm("mov.b64 %0, {%1, %2};" : "=l"(r) : "f"(lo), "f"(hi)); return r;
}
__device__ __forceinline__ float2 unpack2(ull v) {
    float2 r; asm("mov.b64 {%0, %1}, %2;" : "=f"(r.x), "=f"(r.y) : "l"(v)); return r;
}
#define FFMA2(acc, a, b) asm("fma.rn.f32x2 %0, %1, %2, %0;" : "+l"(acc) : "l"(a), "l"(b))
__device__ __forceinline__ ull add2(ull a, ull b) {
    ull r; asm("add.rn.f32x2 %0, %1, %2;" : "=l"(r) : "l"(a), "l"(b)); return r;
}
struct __align__(16) ull2_t { ull x, y; };

__device__ __forceinline__ unsigned smem_u32(const void* p) {
    unsigned r;
    asm("{ .reg .u64 t; cvta.to.shared.u64 t, %1; cvt.u32.u64 %0, t; }"
        : "=r"(r) : "l"(p));
    return r;
}
__device__ __forceinline__ unsigned mapa_u32(unsigned a, unsigned rk) {
    unsigned o; asm("mapa.shared::cluster.u32 %0, %1, %2;" : "=r"(o) : "r"(a), "r"(rk));
    return o;
}
__device__ __forceinline__ void st_remote_f32(unsigned a, float v) {
    asm volatile("st.shared::cluster.f32 [%0], %1;" :: "r"(a), "f"(v) : "memory");
}
#define CLUSTER_SYNC() do { \
    asm volatile("barrier.cluster.arrive.aligned;" ::: "memory"); \
    asm volatile("barrier.cluster.wait.aligned;"   ::: "memory"); } while (0)

__device__ __forceinline__ float sigm_f(float x) {
    return 1.0f / (1.0f + __expf(-x));
}
__device__ __forceinline__ float tanh_f(float x) {
    return 2.0f / (1.0f + __expf(-2.0f * x)) - 1.0f;
}

// ---------------- kernel 1: alpha (softmax over inputs) + X_tilde --------
// alpha[b,n] = softmax_n( sum_t X[b,t,n] * W_attn[2H + t] )  (h/c/b_attn terms
// are constant over n and cancel in the softmax).
__global__ __launch_bounds__(256) void alpha_kernel(const float* __restrict__ X,
                                                    const float* __restrict__ W_attn,
                                                    float* __restrict__ out_xt) {
    __shared__ float wx[TM1];
    __shared__ float red[256];
    const int b = blockIdx.x;
    const int n = threadIdx.x;
    if (n < TM1) wx[n] = W_attn[2 * Hd + n];
    __syncthreads();

    const float* Xb = X + (size_t)b * TM1 * NIN;
    // 8 independent accumulators -> MLP 8 on the serial chain
    float e0 = 0.f, e1 = 0.f, e2 = 0.f, e3 = 0.f;
    float e4 = 0.f, e5 = 0.f, e6 = 0.f, e7 = 0.f;
    int t = 0;
#pragma unroll 1
    for (; t + 8 <= TM1; t += 8) {
        e0 = fmaf(Xb[(t + 0) * NIN + n], wx[t + 0], e0);
        e1 = fmaf(Xb[(t + 1) * NIN + n], wx[t + 1], e1);
        e2 = fmaf(Xb[(t + 2) * NIN + n], wx[t + 2], e2);
        e3 = fmaf(Xb[(t + 3) * NIN + n], wx[t + 3], e3);
        e4 = fmaf(Xb[(t + 4) * NIN + n], wx[t + 4], e4);
        e5 = fmaf(Xb[(t + 5) * NIN + n], wx[t + 5], e5);
        e6 = fmaf(Xb[(t + 6) * NIN + n], wx[t + 6], e6);
        e7 = fmaf(Xb[(t + 7) * NIN + n], wx[t + 7], e7);
    }
    for (; t < TM1; t++) e0 = fmaf(Xb[t * NIN + n], wx[t], e0);
    float e = ((e0 + e1) + (e2 + e3)) + ((e4 + e5) + (e6 + e7));

    red[n] = e; __syncthreads();
    for (int s = 128; s > 0; s >>= 1) {
        if (n < s) red[n] = fmaxf(red[n], red[n + s]);
        __syncthreads();
    }
    float m = red[0];
    __syncthreads();
    float p = __expf(e - m);
    red[n] = p; __syncthreads();
    for (int s = 128; s > 0; s >>= 1) {
        if (n < s) red[n] += red[n + s];
        __syncthreads();
    }
    const float a = p / red[0];

    float* outb = out_xt + (size_t)b * TM1 * NIN;
#pragma unroll 5
    for (int tt = 0; tt < TM1; tt++) outb[tt * NIN + n] = a * Xb[tt * NIN + n];
}

// ---------------- kernel 2: G = X_tilde @ W_lstm + b_lstm ----------------
// 128 threads, 128x128 CTA tile, 16x8 per-thread tile. Accumulators hold
// ROW-PAIRS packed f32x2 (a-pairs read directly from smem, no per-a pack).
__global__ __launch_bounds__(128, 2) void gemm_kernel(const float* __restrict__ A,
                                                      const float* __restrict__ W,
                                                      const float* __restrict__ bias) {
    __shared__ float As[8][128];
    __shared__ float Bs[8][128];
    const int tid  = threadIdx.x;
    const int row0 = blockIdx.y * 128;
    const int col0 = blockIdx.x * 128;

    const int tr = (tid >> 4) << 4;      // 16-row group
    const int tc = (tid & 15) << 3;      // 8-col group
    const int bk = tid >> 4;             // B staging: row within k-slab
    const int bc = (tid & 15) << 3;

    ull acc[8][8];                       // [row-pair][col]
#pragma unroll
    for (int ip = 0; ip < 8; ip++)
#pragma unroll
        for (int j = 0; j < 8; j++) acc[ip][j] = 0ULL;

    for (int k0 = 0; k0 < 256; k0 += 8) {
        // stage A: thread owns one row, 8 k values, store transposed
        float4 a0 = *(const float4*)(A + (size_t)(row0 + tid) * 256 + k0);
        float4 a1 = *(const float4*)(A + (size_t)(row0 + tid) * 256 + k0 + 4);
        As[0][tid] = a0.x; As[1][tid] = a0.y; As[2][tid] = a0.z; As[3][tid] = a0.w;
        As[4][tid] = a1.x; As[5][tid] = a1.y; As[6][tid] = a1.z; As[7][tid] = a1.w;
        // stage B: row bk, cols bc..bc+7
        *(float4*)&Bs[bk][bc]     = *(const float4*)(W + (size_t)(k0 + bk) * 1024 + col0 + bc);
        *(float4*)&Bs[bk][bc + 4] = *(const float4*)(W + (size_t)(k0 + bk) * 1024 + col0 + bc + 4);
        __syncthreads();

#pragma unroll
        for (int k = 0; k < 8; k++) {
            // a row-pairs: 16 consecutive rows = 8 ull, straight from smem
            ull2_t qa0 = *(const ull2_t*)&As[k][tr];
            ull2_t qa1 = *(const ull2_t*)&As[k][tr + 4];
            ull2_t qa2 = *(const ull2_t*)&As[k][tr + 8];
            ull2_t qa3 = *(const ull2_t*)&As[k][tr + 12];
            ull av[8] = { qa0.x, qa0.y, qa1.x, qa1.y, qa2.x, qa2.y, qa3.x, qa3.y };
            float4 b0 = *(const float4*)&Bs[k][tc];
            float4 b1 = *(const float4*)&Bs[k][tc + 4];
            ull bp[8];
            bp[0] = pack2(b0.x, b0.x); bp[1] = pack2(b0.y, b0.y);
            bp[2] = pack2(b0.z, b0.z); bp[3] = pack2(b0.w, b0.w);
            bp[4] = pack2(b1.x, b1.x); bp[5] = pack2(b1.y, b1.y);
            bp[6] = pack2(b1.z, b1.z); bp[7] = pack2(b1.w, b1.w);
#pragma unroll
            for (int ip = 0; ip < 8; ip++)
#pragma unroll
                for (int j = 0; j < 8; j++) FFMA2(acc[ip][j], av[ip], bp[j]);
        }
        __syncthreads();
    }

    float bias8[8];
    *(float4*)&bias8[0] = *(const float4*)&bias[col0 + tc];
    *(float4*)&bias8[4] = *(const float4*)&bias[col0 + tc + 4];
#pragma unroll
    for (int ip = 0; ip < 8; ip++) {
        float lo[8], hi[8];
#pragma unroll
        for (int j = 0; j < 8; j++) {
            float2 f = unpack2(acc[ip][j]);
            lo[j] = f.x + bias8[j];
            hi[j] = f.y + bias8[j];
        }
        const size_t r0 = (size_t)(row0 + tr + 2 * ip) * G4H + col0 + tc;
        *(float4*)&g_G[r0]            = *(float4*)&lo[0];
        *(float4*)&g_G[r0 + 4]        = *(float4*)&lo[4];
        *(float4*)&g_G[r0 + G4H]      = *(float4*)&hi[0];
        *(float4*)&g_G[r0 + G4H + 4]  = *(float4*)&hi[4];
    }
}

// ---------------- kernel 3: cluster-based LSTM recurrence ----------------
// 128 CTAs = 16 clusters of 8 (HW co-schedules each cluster; no deadlock).
// Cluster = one b-block (8 batches); rank = j-block (32 hidden units).
// Thread = (jj 0..31, ke 0..7 k-eighth). U coefficients live in REGISTERS as
// (u_k, u_{k+1}) f32x2 pairs -> zero U smem traffic in the loop. h exchanged
// via DSMEM stores + barrier.cluster each step.
#define HB_ULL    2048                       /* ull hbuf[2][128][8]           */
#define RED_ROW   258                        /* 8b*4g*8ke = 256 ull + pad     */
#define RED_ULL   (32 * RED_ROW)             /* 8256 ull                      */
#define RSMEM_BYTES (HB_ULL * 8 + RED_ULL * 8 + 64)   /* 82496 B             */

__global__ void __launch_bounds__(256, 1) __cluster_dims__(8, 1, 1)
recur_kernel(const float* __restrict__ X,
             const float* __restrict__ U,
             float* __restrict__ out_enc) {
    extern __shared__ char smem[];
    ull*      hbuf = (ull*)smem;                       // [buf][kp][b]
    ull*      red  = hbuf + HB_ULL;                    // [jj][b][ke][g] (+pad)
    unsigned* rkb  = (unsigned*)(red + RED_ULL);       // [buf][rank] DSMEM bases

    const int tid = threadIdx.x;
    const int jj  = tid & 31;
    const int ke  = tid >> 5;            // k-eighth: k in [ke*32, ke*32+32)
    unsigned rank; asm("mov.u32 %0, %%cluster_ctarank;" : "=r"(rank));
    const int j0 = (int)rank * 32;
    const int b0 = (blockIdx.x >> 3) * 8;
    const int j  = j0 + jj;

    // ---- load this thread's U block into registers as k-pairs ----
    ull Ureg[64];                        // [kpl][g]
#pragma unroll
    for (int kpl = 0; kpl < 16; kpl++) {
        const int k0 = (ke * 16 + kpl) * 2;
        const float* U0 = U + (size_t)k0 * 1024 + j;
        const float* U1 = U0 + 1024;
#pragma unroll
        for (int g = 0; g < 4; g++)
            Ureg[kpl * 4 + g] = pack2(U0[g * 256], U1[g * 256]);
    }

    // ---- init h0 = c0 = X[b,0,0]; DSMEM base table ----
    for (int idx = tid; idx < 1024; idx += 256) {
        const int b = idx & 7;
        const float x0 = X[(size_t)(b0 + b) * (TM1 * NIN)];
        hbuf[idx] = pack2(x0, x0);       // buf 0, kp = idx>>3
    }
    if (tid < 16) {
        const int buf = tid >> 3, r = tid & 7;
        rkb[tid] = mapa_u32(smem_u32(hbuf + buf * 1024), (unsigned)r);
    }
    // epilogue cell for this thread: (jj2, b2)
    const int jj2 = tid & 31;
    const int b2  = tid >> 5;
    const int j2  = j0 + jj2;
    float c = X[(size_t)(b0 + b2) * (TM1 * NIN)];
    const unsigned h_off = (unsigned)((((j2 >> 1) * 8 + b2) * 8) + (j2 & 1) * 4);

    __syncthreads();
    CLUSTER_SYNC();

    for (int t = 0; t < TM1; t++) {
        // prefetch this step's gate pre-activations (global, coalesced)
        const float* gr = g_G + ((size_t)(b0 + b2) * TM1 + t) * G4H + j2;
        const float G0 = gr[0],   G1 = gr[256];
        const float G2 = gr[512], G3 = gr[768];

        // ---- partial h@U over this thread's 32 k values ----
        ull acc[32];                     // [b][g]
#pragma unroll
        for (int i = 0; i < 32; i++) acc[i] = 0ULL;

        const ull* hb = hbuf + ((t & 1) << 10) + (ke << 7);
#pragma unroll
        for (int kpl = 0; kpl < 16; kpl++) {
            const ull2_t h01 = *(const ull2_t*)(hb + kpl * 8);
            const ull2_t h23 = *(const ull2_t*)(hb + kpl * 8 + 2);
            const ull2_t h45 = *(const ull2_t*)(hb + kpl * 8 + 4);
            const ull2_t h67 = *(const ull2_t*)(hb + kpl * 8 + 6);
            const ull u0 = Ureg[kpl * 4 + 0], u1 = Ureg[kpl * 4 + 1];
            const ull u2 = Ureg[kpl * 4 + 2], u3 = Ureg[kpl * 4 + 3];
            FFMA2(acc[ 0], h01.x, u0); FFMA2(acc[ 1], h01.x, u1);
            FFMA2(acc[ 2], h01.x, u2); FFMA2(acc[ 3], h01.x, u3);
            FFMA2(acc[ 4], h01.y, u0); FFMA2(acc[ 5], h01.y, u1);
            FFMA2(acc[ 6], h01.y, u2); FFMA2(acc[ 7], h01.y, u3);
            FFMA2(acc[ 8], h23.x, u0); FFMA2(acc[ 9], h23.x, u1);
            FFMA2(acc[10], h23.x, u2); FFMA2(acc[11], h23.x, u3);
            FFMA2(acc[12], h23.y, u0); FFMA2(acc[13], h23.y, u1);
            FFMA2(acc[14], h23.y, u2); FFMA2(acc[15], h23.y, u3);
            FFMA2(acc[16], h45.x, u0); FFMA2(acc[17], h45.x, u1);
            FFMA2(acc[18], h45.x, u2); FFMA2(acc[19], h45.x, u3);
            FFMA2(acc[20], h45.y, u0); FFMA2(acc[21], h45.y, u1);
            FFMA2(acc[22], h45.y, u2); FFMA2(acc[23], h45.y, u3);
            FFMA2(acc[24], h67.x, u0); FFMA2(acc[25], h67.x, u1);
            FFMA2(acc[26], h67.x, u2); FFMA2(acc[27], h67.x, u3);
            FFMA2(acc[28], h67.y, u0); FFMA2(acc[29], h67.y, u1);
            FFMA2(acc[30], h67.y, u2); FFMA2(acc[31], h67.y, u3);
        }

        // ---- write k-eighth partials (conflict-free padded layout) ----
        {
            ull* rw = red + jj * RED_ROW + ke * 4;
#pragma unroll
            for (int b = 0; b < 8; b++) {
                ull2_t v0; v0.x = acc[b * 4 + 0]; v0.y = acc[b * 4 + 1];
                ull2_t v1; v1.x = acc[b * 4 + 2]; v1.y = acc[b * 4 + 3];
                *(ull2_t*)(rw + b * 32)     = v0;
                *(ull2_t*)(rw + b * 32 + 2) = v1;
            }
        }
        __syncthreads();

        // ---- epilogue: one (j, batch) cell per thread ----
        const ull* rr = red + jj2 * RED_ROW + b2 * 32;
        ull s0 = 0ULL, s1 = 0ULL, s2 = 0ULL, s3 = 0ULL;
#pragma unroll
        for (int k8 = 0; k8 < 8; k8++) {
            ull2_t p = *(const ull2_t*)(rr + k8 * 4);
            ull2_t q = *(const ull2_t*)(rr + k8 * 4 + 2);
            s0 = add2(s0, p.x); s1 = add2(s1, p.y);
            s2 = add2(s2, q.x); s3 = add2(s3, q.y);
        }
        float2 f0 = unpack2(s0), f1 = unpack2(s1);
        float2 f2 = unpack2(s2), f3 = unpack2(s3);
        const float zi = f0.x + f0.y + G0;
        const float zf = f1.x + f1.y + G1;
        const float zg = f2.x + f2.y + G2;
        const float zo = f3.x + f3.y + G3;

        c = sigm_f(zf) * c + sigm_f(zi) * tanh_f(zg);
        const float hn = sigm_f(zo) * tanh_f(c);

        out_enc[((size_t)(b0 + b2) * TM1 + t) * Hd + j2] = hn;

        // broadcast h_{t+1} to every rank's next buffer (incl. self)
        const unsigned* rkn = rkb + ((t + 1) & 1) * 8;
#pragma unroll
        for (int r = 0; r < 8; r++)
            st_remote_f32(rkn[r] + h_off, hn);

        CLUSTER_SYNC();   // release h writes; acquire before next reads
    }
}

// ---------------- launch ----------------
extern "C" void kernel_launch(void* const* d_in, const int* in_sizes, int n_in,
                              void* d_out, int out_size) {
    const float* X      = (const float*)d_in[0];
    const float* W_attn = (const float*)d_in[1];
    /* b_attn = d_in[2] : cancels in softmax */
    const float* W_lstm = (const float*)d_in[3];
    const float* U_lstm = (const float*)d_in[4];
    const float* b_lstm = (const float*)d_in[5];

    float* out     = (float*)d_out;
    float* out_xt  = out;                             // X_tilde  (B,Tm1,N)
    float* out_enc = out + (size_t)Bsz * TM1 * NIN;   // X_encoded (B,Tm1,H)

    cudaFuncSetAttribute(recur_kernel,
                         cudaFuncAttributeMaxDynamicSharedMemorySize, RSMEM_BYTES);

    alpha_kernel<<<Bsz, 256>>>(X, W_attn, out_xt);
    gemm_kernel<<<dim3(8, TM1), 128>>>(out_xt, W_lstm, b_lstm);
    recur_kernel<<<128, 256, RSMEM_BYTES>>>(X, U_lstm, out_enc);
}